// round 2
// baseline (speedup 1.0000x reference)
#include <cuda_runtime.h>
#include <cuda_fp16.h>
#include <cstdint>

// ---------------- problem constants ----------------
#define N_ROWS 16384
#define DF     128
#define KC     32                 // K chunk per pipeline stage
#define NITER  (N_ROWS / KC)      // 512

// XW = x @ W, packed as half2 pairs along j (row j/2 holds {XW[2k][d], XW[2k+1][d]}).
__device__ uint32_t g_XWp[(size_t)(N_ROWS / 2) * DF];   // 4 MiB

__device__ __forceinline__ uint32_t packh2(float lo, float hi) {
    __half2 h = __floats2half2_rn(lo, hi);   // .x (low) = lo, .y (high) = hi
    return *(uint32_t*)&h;
}

// ---------------- kernel 1: XW = x @ W (fp32 compute, fp16-pair store) ----------------
// grid 128, block 256 (16x16 threads, each an 8x8 register tile).
#define XW_SMEM ((128 * 132 + 128 * 128) * 4)

__global__ void __launch_bounds__(256) xw_kernel(const float* __restrict__ x,
                                                 const float* __restrict__ W) {
    extern __shared__ float sm_xw[];
    float* xsT = sm_xw;              // [128][132] transposed x tile (padded)
    float* Ws  = sm_xw + 128 * 132;  // [128][128]
    const int tid = threadIdx.x;
    const int j0 = blockIdx.x * 128;

    for (int idx = tid; idx < 128 * 128; idx += 256) {
        int j = idx >> 7, k = idx & 127;
        xsT[k * 132 + j] = x[(size_t)(j0 + j) * DF + k];
        Ws[idx] = W[idx];
    }
    __syncthreads();

    const int tx = tid & 15, ty = tid >> 4;
    const int jb = ty * 8, db = tx * 8;
    float acc[8][8];
#pragma unroll
    for (int a = 0; a < 8; a++)
#pragma unroll
        for (int b = 0; b < 8; b++) acc[a][b] = 0.0f;

    for (int k = 0; k < 128; k++) {
        float4 a0 = *(const float4*)(xsT + k * 132 + jb);
        float4 a1 = *(const float4*)(xsT + k * 132 + jb + 4);
        float4 b0 = *(const float4*)(Ws + k * 128 + db);
        float4 b1 = *(const float4*)(Ws + k * 128 + db + 4);
        float aa[8] = {a0.x, a0.y, a0.z, a0.w, a1.x, a1.y, a1.z, a1.w};
        float bb[8] = {b0.x, b0.y, b0.z, b0.w, b1.x, b1.y, b1.z, b1.w};
#pragma unroll
        for (int jj = 0; jj < 8; jj++)
#pragma unroll
            for (int dd = 0; dd < 8; dd++) acc[jj][dd] += aa[jj] * bb[dd];
    }

    // pack pairs along j: rows (jb+2q, jb+2q+1) -> pair-row (j0+jb)/2 + q
    const uint32_t jp = (uint32_t)((j0 + jb) >> 1);
#pragma unroll
    for (int q = 0; q < 4; q++) {
        uint32_t* dst = g_XWp + (size_t)(jp + q) * DF + db;
        uint4 v0, v1;
        v0.x = packh2(acc[2 * q][0], acc[2 * q + 1][0]);
        v0.y = packh2(acc[2 * q][1], acc[2 * q + 1][1]);
        v0.z = packh2(acc[2 * q][2], acc[2 * q + 1][2]);
        v0.w = packh2(acc[2 * q][3], acc[2 * q + 1][3]);
        v1.x = packh2(acc[2 * q][4], acc[2 * q + 1][4]);
        v1.y = packh2(acc[2 * q][5], acc[2 * q + 1][5]);
        v1.z = packh2(acc[2 * q][6], acc[2 * q + 1][6]);
        v1.w = packh2(acc[2 * q][7], acc[2 * q + 1][7]);
        *(uint4*)dst = v0;
        *(uint4*)(dst + 4) = v1;
    }
}

// ---------------- kernel 2: fused exp + softmax-GEMM (mma.sync f16) ----------------
// CTA: 128 rows x 128 out-cols, K streamed in chunks of 32.
// A smem: [128 m][16 u32] (half2 pairs along k), stride 20 u32 (conflict-free frags).
// B smem: [16 kk][128 n] u32 half2 pairs, stride 136 u32 (conflict-free frags).

#define SA2 20
#define SB2 136
#define A_ST (128 * SA2)         // 2560 u32 per stage
#define B_ST (16 * SB2)          // 2176 u32 per stage
#define A_OFF 0
#define B_OFF (2 * A_ST)         // 5120
#define RS_OFF (B_OFF + 2 * B_ST)  // 9472
#define BIAS_OFF (RS_OFF + 128)    // 9600
#define FUSED_SMEM ((BIAS_OFF + 128) * 4)  // 38912 B

__global__ void __launch_bounds__(256) fused_kernel(const float* __restrict__ adj,
                                                    const float* __restrict__ bias,
                                                    float* __restrict__ out) {
    extern __shared__ uint32_t sm[];
    float* smf = (float*)sm;
    const int tid = threadIdx.x;
    const int wid = tid >> 5;
    const int lid = tid & 31;
    const int m0 = blockIdx.x * 128;

    if (tid < DF) smf[BIAS_OFF + tid] = bias[tid];

    // ---- producer mappings ----
    const int r = tid >> 1;            // adj row within tile (0..127)
    const int hf = tid & 1;            // which 16-float half of the 32 chunk cols
    const float* aptr = adj + (size_t)(m0 + r) * N_ROWS + hf * 16;
    const uint32_t a_sts = (uint32_t)r * SA2 + hf * 8;

    const int kk = tid >> 4;           // pair-row within B chunk (0..15)
    const int nb = tid & 15;           // 8-u32 col block
    const uint32_t* bptr = g_XWp + (size_t)kk * DF + nb * 8;
    const uint32_t b_sts = (uint32_t)kk * SB2 + nb * 8;

    // ---- consumer mapping ----
    const int g = lid >> 2, tg = lid & 3;
    const int mB = (wid & 3) * 32;
    const int nB = (wid >> 2) * 64;

    float4 ar[4];
    uint4 br[2];
    float rsum = 0.0f;
    float acc[2][8][4];
#pragma unroll
    for (int i = 0; i < 2; i++)
#pragma unroll
        for (int j = 0; j < 8; j++)
#pragma unroll
            for (int c = 0; c < 4; c++) acc[i][j][c] = 0.0f;

    // prologue: fetch chunk 0
#pragma unroll
    for (int q = 0; q < 4; q++) ar[q] = *(const float4*)(aptr + q * 4);
    br[0] = *(const uint4*)(bptr);
    br[1] = *(const uint4*)(bptr + 4);

    // produce: exp + pack + STS the chunk currently held in (ar, br) into stage s
#define PRODUCE(s) do {                                                          \
        uint32_t pk[8];                                                          \
        _Pragma("unroll")                                                        \
        for (int q = 0; q < 4; q++) {                                            \
            float e0 = __expf(ar[q].x), e1 = __expf(ar[q].y);                    \
            float e2 = __expf(ar[q].z), e3 = __expf(ar[q].w);                    \
            rsum += (e0 + e1) + (e2 + e3);                                       \
            pk[2 * q]     = packh2(e0, e1);                                      \
            pk[2 * q + 1] = packh2(e2, e3);                                      \
        }                                                                        \
        uint32_t* As = sm + A_OFF + (s) * A_ST;                                  \
        *(uint4*)(As + a_sts)     = make_uint4(pk[0], pk[1], pk[2], pk[3]);      \
        *(uint4*)(As + a_sts + 4) = make_uint4(pk[4], pk[5], pk[6], pk[7]);      \
        uint32_t* Bs = sm + B_OFF + (s) * B_ST;                                  \
        *(uint4*)(Bs + b_sts)     = br[0];                                       \
        *(uint4*)(Bs + b_sts + 4) = br[1];                                       \
    } while (0)

#define FETCH(itc) do {                                                          \
        const float* ap = aptr + (size_t)(itc) * KC;                             \
        _Pragma("unroll")                                                        \
        for (int q = 0; q < 4; q++) ar[q] = *(const float4*)(ap + q * 4);        \
        const uint32_t* bp = bptr + (size_t)(itc) * 16 * DF;                     \
        br[0] = *(const uint4*)(bp);                                             \
        br[1] = *(const uint4*)(bp + 4);                                         \
    } while (0)

    PRODUCE(0);
    FETCH(1);
    __syncthreads();

    for (int it = 0; it < NITER; ++it) {
        const int s = it & 1;
        if (it + 1 < NITER) PRODUCE(s ^ 1);
        if (it + 2 < NITER) FETCH(it + 2);

        // MMA on stage s
        const uint32_t* As = sm + A_OFF + s * A_ST;
        const uint32_t* Bs = sm + B_OFF + s * B_ST;
#pragma unroll
        for (int ks = 0; ks < 2; ks++) {
            uint32_t af[2][4];
#pragma unroll
            for (int mi = 0; mi < 2; mi++) {
                const uint32_t* Ar = As + (mB + mi * 16 + g) * SA2 + ks * 8 + tg;
                af[mi][0] = Ar[0];
                af[mi][1] = Ar[8 * SA2];
                af[mi][2] = Ar[4];
                af[mi][3] = Ar[8 * SA2 + 4];
            }
#pragma unroll
            for (int ni = 0; ni < 8; ni++) {
                const uint32_t* Br = Bs + (ks * 8 + tg) * SB2 + nB + ni * 8 + g;
                uint32_t b0 = Br[0];
                uint32_t b1 = Br[4 * SB2];
#pragma unroll
                for (int mi = 0; mi < 2; mi++) {
                    asm volatile(
                        "mma.sync.aligned.m16n8k16.row.col.f32.f16.f16.f32 "
                        "{%0,%1,%2,%3}, {%4,%5,%6,%7}, {%8,%9}, {%0,%1,%2,%3};"
                        : "+f"(acc[mi][ni][0]), "+f"(acc[mi][ni][1]),
                          "+f"(acc[mi][ni][2]), "+f"(acc[mi][ni][3])
                        : "r"(af[mi][0]), "r"(af[mi][1]), "r"(af[mi][2]), "r"(af[mi][3]),
                          "r"(b0), "r"(b1));
                }
            }
        }
        __syncthreads();
    }

    // ---- rowsums ----
    rsum += __shfl_xor_sync(0xffffffffu, rsum, 1);
    if (hf == 0) smf[RS_OFF + r] = rsum;
    __syncthreads();

    // ---- epilogue: divide + bias + store ----
#pragma unroll
    for (int mi = 0; mi < 2; mi++) {
        const int r0 = mB + mi * 16 + g;
        const int r1 = r0 + 8;
        const float inv0 = 1.0f / smf[RS_OFF + r0];
        const float inv1 = 1.0f / smf[RS_OFF + r1];
#pragma unroll
        for (int ni = 0; ni < 8; ni++) {
            const int c = nB + ni * 8 + 2 * tg;
            const float b0v = smf[BIAS_OFF + c];
            const float b1v = smf[BIAS_OFF + c + 1];
            float2 o;
            o.x = acc[mi][ni][0] * inv0 + b0v;
            o.y = acc[mi][ni][1] * inv0 + b1v;
            *(float2*)(out + (size_t)(m0 + r0) * DF + c) = o;
            o.x = acc[mi][ni][2] * inv1 + b0v;
            o.y = acc[mi][ni][3] * inv1 + b1v;
            *(float2*)(out + (size_t)(m0 + r1) * DF + c) = o;
        }
    }
}

// ---------------- launcher ----------------
extern "C" void kernel_launch(void* const* d_in, const int* in_sizes, int n_in,
                              void* d_out, int out_size) {
    const float* x   = (const float*)d_in[0];
    const float* adj = (const float*)d_in[1];
    const float* W   = (const float*)d_in[2];
    const float* b   = (const float*)d_in[3];
    float* out = (float*)d_out;
    (void)in_sizes; (void)n_in; (void)out_size;

    cudaFuncSetAttribute(xw_kernel, cudaFuncAttributeMaxDynamicSharedMemorySize, XW_SMEM);

    xw_kernel<<<N_ROWS / 128, 256, XW_SMEM>>>(x, W);
    fused_kernel<<<N_ROWS / 128, 256, FUSED_SMEM>>>(adj, b, out);
}